// round 1
// baseline (speedup 1.0000x reference)
#include <cuda_runtime.h>
#include <math.h>

// SoftPolygon: B=32 polygons of P=32 vertices rasterized to 128x128 soft masks.
// out[b,y,x] = sigmoid(min_seg_dist_sq * (inside ? +1 : -1))
//
// Structure: one block per (batch, row). Per-row/per-edge constants (crossing
// x-intercept, projection coefficients) precomputed once into shared float4s;
// each of the 128 threads handles one pixel column, fully unrolled over 32 edges.
//
// Numerical contract with the JAX reference:
//  - crossing test must be BIT-EXACT (a parity flip = O(1) output error):
//    xint computed with __fmul_rn/__fdiv_rn/__fadd_rn in reference op order;
//    it is gx-independent, so hoisting per row changes nothing.
//  - segment distance is continuous in `dot`, so 1/sq_len may be precomputed
//    (ulp-level perturbation only).

namespace {

constexpr int NB = 32;   // batch
constexpr int NP = 32;   // vertices / edges per polygon
constexpr int NH = 128;  // height
constexpr int NW = 128;  // width

__global__ __launch_bounds__(NW) void soft_poly_kernel(
    const float* __restrict__ verts,   // (B, P, 2)
    float* __restrict__ out)           // (B, H, W)
{
    const int row = blockIdx.x;        // gy
    const int b   = blockIdx.y;
    const float gy = (float)row;
    const int tid = threadIdx.x;       // gx

    __shared__ float vx[NP], vy[NP];
    __shared__ float4 e0[NP];  // {xint_eff, x1, dx*inv, ys1*dy*inv}
    __shared__ float4 e1[NP];  // {ys1, ys1*ys1, x2, ys2*ys2}
    __shared__ float4 e2[NP];  // {dx, dy, -, -}

    if (tid < NP) {
        const float* vb = verts + ((size_t)b * NP + tid) * 2;
        vx[tid] = vb[0];
        vy[tid] = vb[1];
    }
    __syncthreads();

    if (tid < NP) {
        const int i  = tid;
        const int jp = (i + NP - 1) & (NP - 1);  // prev vertex (roll +1)
        const int kn = (i + 1) & (NP - 1);       // next vertex (roll -1)

        const float fx = vx[i],  fy = vy[i];
        const float tx = vx[jp], ty = vy[jp];

        // Crossing-number test, gx-independent part. EXACT op order of the
        // reference: mul, div, add — each individually rounded (immune to
        // fast-math / contraction via explicit _rn intrinsics).
        const bool cond = (fy > gy) != (ty > gy);
        float xint = __fadd_rn(
            __fdiv_rn(__fmul_rn(tx - fx, gy - fy), ty - fy), fx);
        if (!cond) xint = -3.402823466e38f;  // gx >= 0 can never be < this

        // Segment-distance constants for edge (v_i -> v_{i+1}).
        const float x1 = fx, y1 = fy;
        const float x2 = vx[kn], y2 = vy[kn];
        const float dx = x2 - x1, dy = y2 - y1;
        const float sq  = dx * dx + dy * dy + 1e-5f;
        const float inv = __fdiv_rn(1.0f, sq);
        const float ys1 = gy - y1, ys2 = gy - y2;

        e0[i] = make_float4(xint, x1, dx * inv, ys1 * dy * inv);
        e1[i] = make_float4(ys1, ys1 * ys1, x2, ys2 * ys2);
        e2[i] = make_float4(dx, dy, 0.0f, 0.0f);
    }
    __syncthreads();

    const float gx = (float)tid;
    float mn = 3.402823466e38f;
    int cnt = 0;

#pragma unroll
    for (int i = 0; i < NP; ++i) {
        const float4 a0 = e0[i];
        const float4 a1 = e1[i];
        const float4 a2 = e2[i];

        // parity: gx < xint (xint bit-identical to reference expression)
        cnt += (gx < a0.x) ? 1 : 0;

        // squared point-to-segment distance
        const float xs1 = gx - a0.y;                 // gx - x1
        const float dot = fmaf(xs1, a0.z, a0.w);     // (xs1*dx + ys1*dy)/sq
        const float d1  = fmaf(xs1, xs1, a1.y);      // |g - v1|^2
        const float xs2 = gx - a1.z;                 // gx - x2
        const float d2  = fmaf(xs2, xs2, a1.w);      // |g - v2|^2
        const float xpj = fmaf(-dot, a2.x, xs1);     // xs1 - dot*dx
        const float ypj = fmaf(-dot, a2.y, a1.x);    // ys1 - dot*dy
        const float dp  = fmaf(xpj, xpj, ypj * ypj); // projection dist^2

        const float seg = (dot < 0.0f) ? d1 : ((dot > 1.0f) ? d2 : dp);
        mn = fminf(mn, seg);
    }

    const float io = (cnt & 1) ? 1.0f : -1.0f;
    const float x  = mn * io;
    const float F  = 1.0f / (1.0f + expf(-x));

    out[((size_t)b * NH + row) * NW + tid] = F;
}

}  // namespace

extern "C" void kernel_launch(void* const* d_in, const int* in_sizes, int n_in,
                              void* d_out, int out_size) {
    const float* verts = (const float*)d_in[0];
    float* out = (float*)d_out;
    dim3 grid(NH, NB);  // 128 rows x 32 batches = 4096 blocks
    soft_poly_kernel<<<grid, NW>>>(verts, out);
}

// round 3
// speedup vs baseline: 1.8162x; 1.8162x over previous
#include <cuda_runtime.h>
#include <cstdint>
#include <math.h>

// SoftPolygon B=32, P=32, 128x128.  out[b,y,x] = sigmoid(min_seg_sq * io)
//
// v2.1: - parity hoisted out of mainloop via exact integer-threshold + XOR-mask
//         (c < xint for integer c  <=>  c < clamp(ceil(xint),0,128), bit-exact)
//       - clamped-t segment distance (continuous; no selects)
//       - 4 pixels per lane, warp-per-row: LDS amortized 4x
//
// Numerical contract: parity bit-identical to reference; distances/sigmoid
// differ by ulps on continuous paths only.

namespace {

constexpr int NB = 32;
constexpr int NP = 32;
constexpr int NH = 128;
constexpr int NW = 128;
constexpr int RPB = 4;     // rows per block (one warp per row)

__global__ __launch_bounds__(128) void soft_poly_kernel(
    const float* __restrict__ verts,   // (B, P, 2)
    float* __restrict__ out)           // (B, H, W)
{
    const int b    = blockIdx.y;
    const int row0 = blockIdx.x * RPB;
    const int tid  = threadIdx.x;
    const int r    = tid >> 5;         // warp index = local row
    const int lane = tid & 31;
    const int row  = row0 + r;
    const float gy = (float)row;

    __shared__ float  vbuf[NP * 2];            // interleaved x,y
    __shared__ float4 sA[RPB][NP];             // {x1, dx*inv, ys1*dy*inv, dx}
    __shared__ float2 sB[RPB][NP];             // {dy, ys1}

    if (tid < NP * 2) vbuf[tid] = verts[(size_t)b * NP * 2 + tid];
    __syncthreads();

    // ---- per-(row, edge) precompute; edge index = lane, done by warp r ----
    unsigned int pm0, pm1, pm2, pm3;  // row parity mask; word k covers cols [32k,32k+32)
    {
        const int i  = lane;
        const int jp = (i + NP - 1) & (NP - 1);   // prev vertex (roll +1)
        const int kn = (i + 1) & (NP - 1);        // next vertex (roll -1)
        const float fx = vbuf[2 * i],  fy = vbuf[2 * i + 1];
        const float tx = vbuf[2 * jp], ty = vbuf[2 * jp + 1];
        const float x2 = vbuf[2 * kn], y2 = vbuf[2 * kn + 1];

        // crossing threshold, EXACT reference op order (mul, div, add)
        const bool cond = (fy > gy) != (ty > gy);
        float xint = __fadd_rn(
            __fdiv_rn(__fmul_rn(tx - fx, gy - fy), ty - fy), fx);
        if (!cond) xint = -1.0f;
        // #columns c in [0,128) with (float)c < xint  — exact
        const float xc = fminf(fmaxf(ceilf(xint), 0.0f), 128.0f);
        const int ci = (int)xc;

        // 128-bit mask of bits [0, ci), XOR-reduced across the warp = parity
        const int n0 = min(max(ci,       0), 32);
        const int n1 = min(max(ci - 32,  0), 32);
        const int n2 = min(max(ci - 64,  0), 32);
        const int n3 = min(max(ci - 96,  0), 32);
        const unsigned int m0 = (unsigned int)((1ull << n0) - 1ull);
        const unsigned int m1 = (unsigned int)((1ull << n1) - 1ull);
        const unsigned int m2 = (unsigned int)((1ull << n2) - 1ull);
        const unsigned int m3 = (unsigned int)((1ull << n3) - 1ull);
        pm0 = __reduce_xor_sync(0xffffffffu, m0);
        pm1 = __reduce_xor_sync(0xffffffffu, m1);
        pm2 = __reduce_xor_sync(0xffffffffu, m2);
        pm3 = __reduce_xor_sync(0xffffffffu, m3);

        // segment-distance constants for edge (v_i -> v_{i+1})
        const float dx = x2 - fx, dy = y2 - fy;
        const float sq  = dx * dx + dy * dy + 1e-5f;
        const float inv = __fdiv_rn(1.0f, sq);
        const float ys1 = gy - fy;
        sA[r][i] = make_float4(fx, dx * inv, ys1 * dy * inv, dx);
        sB[r][i] = make_float2(dy, ys1);
    }
    __syncwarp();   // sA/sB written and read by the same warp

    // ---- mainloop: 4 pixels per lane (columns lane + 32k) ----
    const float gx0 = (float)lane;
    const float gx1 = gx0 + 32.0f;
    const float gx2 = gx0 + 64.0f;
    const float gx3 = gx0 + 96.0f;
    float mn0 = 3.402823466e38f, mn1 = mn0, mn2 = mn0, mn3 = mn0;

#pragma unroll
    for (int i = 0; i < NP; ++i) {
        const float4 a  = sA[r][i];
        const float2 bb = sB[r][i];

#define PIX(GX, MN) do {                                   \
        const float xs  = (GX) - a.x;                      \
        const float dot = fmaf(xs, a.y, a.z);              \
        const float t   = __saturatef(dot);                \
        const float xp  = fmaf(-t, a.w, xs);               \
        const float yp  = fmaf(-t, bb.x, bb.y);            \
        const float d   = fmaf(xp, xp, yp * yp);           \
        (MN) = fminf((MN), d);                             \
    } while (0)

        PIX(gx0, mn0);
        PIX(gx1, mn1);
        PIX(gx2, mn2);
        PIX(gx3, mn3);
#undef PIX
    }

    // ---- epilogue: sign from parity mask, sigmoid, store ----
    float* op = out + ((size_t)b * NH + row) * NW + lane;
#define EMIT(PM, MN, K) do {                                         \
        const float io = ((PM >> lane) & 1u) ? 1.0f : -1.0f;         \
        const float x  = (MN) * io;                                  \
        op[(K) * 32] = __fdividef(1.0f, 1.0f + __expf(-x));          \
    } while (0)
    EMIT(pm0, mn0, 0);
    EMIT(pm1, mn1, 1);
    EMIT(pm2, mn2, 2);
    EMIT(pm3, mn3, 3);
#undef EMIT
}

}  // namespace

extern "C" void kernel_launch(void* const* d_in, const int* in_sizes, int n_in,
                              void* d_out, int out_size) {
    const float* verts = (const float*)d_in[0];
    float* out = (float*)d_out;
    dim3 grid(NH / RPB, NB);   // 32 x 32 = 1024 blocks, 4 warps each
    soft_poly_kernel<<<grid, 128>>>(verts, out);
}